// round 12
// baseline (speedup 1.0000x reference)
#include <cuda_runtime.h>
#include <cuda_fp16.h>
#include <cstddef>
#include <cstdint>

#define BB 64
#define PP 2000
#define DD 128
#define TT 200
#define TILES 32
#define EPSL 1e-5f

// ---------------- scratch ----------------
__device__ float g_tour [BB * TT * DD];
__device__ unsigned g_tbh[BB * TT * 64];   // fp16x2 tb
__device__ float g_sum  [BB * DD];
__device__ float g_sumsq[BB * DD];
__device__ int   g_cnt  [BB];
// fp16x2 packed weights: [n][kp], kp in [0,64), pair = (W[2kp][n], W[2kp+1][n])
__device__ unsigned g_W1p[DD * 64];   // W1 rows [0,128)
__device__ unsigned g_Wbp[DD * 64];   // W1 rows [128,256)
__device__ unsigned g_W2p[DD * 64];

static __device__ __forceinline__ unsigned pack2(float v0, float v1) {
    __half2 h = __floats2half2_rn(v0, v1);
    return *reinterpret_cast<unsigned*>(&h);
}
static __device__ __forceinline__ float2 unpack2(unsigned u) {
    __half2 h = *reinterpret_cast<__half2*>(&u);
    return make_float2(__half2float(__low2half(h)), __half2float(__high2half(h)));
}

static __device__ __forceinline__ void mma16816(float* c, unsigned a0, unsigned a1,
                                                unsigned a2, unsigned a3,
                                                unsigned b0, unsigned b1) {
    asm volatile(
        "mma.sync.aligned.m16n8k16.row.col.f32.f16.f16.f32 "
        "{%0,%1,%2,%3}, {%4,%5,%6,%7}, {%8,%9}, {%0,%1,%2,%3};"
        : "+f"(c[0]), "+f"(c[1]), "+f"(c[2]), "+f"(c[3])
        : "r"(a0), "r"(a1), "r"(a2), "r"(a3), "r"(b0), "r"(b1));
}

// ---------------- K0: zero scratch (L2-warms g_tour for k_seg atomics) + pack ----------------
__global__ void k_init(const float* __restrict__ W1, const float* __restrict__ W2) {
    int i = blockIdx.x * blockDim.x + threadIdx.x;
    if (i < BB * TT * DD) g_tour[i] = 0.f;
    if (i < BB * DD) { g_sum[i] = 0.f; g_sumsq[i] = 0.f; }
    if (i < BB) g_cnt[i] = 0;
    if (i < 3 * DD * 64) {
        int m  = i >> 13;
        int n  = (i >> 6) & 127;
        int kp = i & 63;
        const float* W = (m == 0) ? W1 : (m == 1) ? (W1 + 128 * DD) : W2;
        unsigned p = pack2(W[(2 * kp) * DD + n], W[(2 * kp + 1) * DD + n]);
        if (m == 0)      g_W1p[n * 64 + kp] = p;
        else if (m == 1) g_Wbp[n * 64 + kp] = p;
        else             g_W2p[n * 64 + kp] = p;
    }
}

// ---------------- K1: segment sum ----------------
__global__ void k_seg(const float* __restrict__ emb, const int* __restrict__ tidx) {
    int i = blockIdx.x * blockDim.x + threadIdx.x;
    int d4 = i & 31;
    int r  = i >> 5;
    if (r >= BB * PP) return;
    int b = r / PP, p = r - b * PP;
    const float4 v = *reinterpret_cast<const float4*>(emb + (size_t)(b * 2001 + 1 + p) * DD + d4 * 4);
    int t = tidx[r];
    float4* dst = reinterpret_cast<float4*>(g_tour + (size_t)(b * TT + t) * DD + d4 * 4);
    atomicAdd(dst, v);
}

// ---------------- K2: tb = tour_emb @ W1b + b1 -> fp16 ----------------
#define TB_OFF_W (32 * 68)
#define TB_SMEM_U32 (TB_OFF_W + 128 * 68)
__global__ void __launch_bounds__(128, 5)
k_tb(const float* __restrict__ b1) {
    extern __shared__ unsigned su[];
    unsigned* As = su;
    unsigned* Ws = su + TB_OFF_W;
    int tid = threadIdx.x;
    int lane = tid & 31, wid = tid >> 5;
    int g = lane >> 2, t4 = lane & 3;
    int wr = wid & 1, wc = wid >> 1;
    int row0 = blockIdx.x * 32;

    for (int i = tid; i < 32 * 32; i += 128) {
        int r = i >> 5, c4 = i & 31;
        float4 v = *reinterpret_cast<const float4*>(g_tour + (size_t)(row0 + r) * DD + c4 * 4);
        As[r * 68 + 2 * c4]     = pack2(v.x, v.y);
        As[r * 68 + 2 * c4 + 1] = pack2(v.z, v.w);
    }
    for (int i = tid; i < 2048; i += 128) {
        int n = i >> 4, k4 = (i & 15) * 4;
        *reinterpret_cast<uint4*>(Ws + n * 68 + k4) =
            *reinterpret_cast<const uint4*>(g_Wbp + n * 64 + k4);
    }
    __syncthreads();

    float acc[8][4];
#pragma unroll
    for (int j = 0; j < 8; j++)
#pragma unroll
        for (int i = 0; i < 4; i++) acc[j][i] = 0.f;
    int r0 = wr * 16 + g, r1 = r0 + 8;

#pragma unroll
    for (int s = 0; s < 8; s++) {
        unsigned a0 = As[r0 * 68 + s * 8 + t4];
        unsigned a1 = As[r1 * 68 + s * 8 + t4];
        unsigned a2 = As[r0 * 68 + s * 8 + t4 + 4];
        unsigned a3 = As[r1 * 68 + s * 8 + t4 + 4];
#pragma unroll
        for (int jt = 0; jt < 8; jt++) {
            int n = wc * 64 + jt * 8 + g;
            mma16816(acc[jt], a0, a1, a2, a3,
                     Ws[n * 68 + s * 8 + t4], Ws[n * 68 + s * 8 + t4 + 4]);
        }
    }

#pragma unroll
    for (int jt = 0; jt < 8; jt++) {
        int colb = wc * 64 + jt * 8 + 2 * t4;
        int cp   = wc * 32 + jt * 4 + t4;
        float2 bb = *reinterpret_cast<const float2*>(b1 + colb);
        g_tbh[(size_t)(row0 + r0) * 64 + cp] = pack2(acc[jt][0] + bb.x, acc[jt][1] + bb.y);
        g_tbh[(size_t)(row0 + r1) * 64 + cp] = pack2(acc[jt][2] + bb.x, acc[jt][3] + bb.y);
    }
}

// ---------------- K3: fused MLP + residual + stats + spin + layernorm ----------------
// smem u32: AH[64*68] (A fp16, overlaid by H fp16), W[128*68], ts[64]  (~52.5 KB -> 4 CTAs/SM)
// After phase2: Ad f32[64][132] = su[0..8447]; redc f32[2048] = su[8448..10495].
#define OFF_W  (64 * 68)
#define OFF_TS (64 * 68 + 128 * 68)
#define SMEM_U32 (OFF_TS + 64)

__global__ void __launch_bounds__(256, 4)
k_main(const float* __restrict__ emb, const int* __restrict__ tidx,
       const float* __restrict__ b2, const float* __restrict__ gamma,
       const float* __restrict__ beta, float* __restrict__ out) {
    extern __shared__ unsigned su[];
    unsigned* Ah = su;                    // A fp16, then H fp16 (overlay)
    unsigned* Ws = su + OFF_W;
    int* ts = (int*)(su + OFF_TS);
    float* Ad   = (float*)su;             // [64][132] after phase2
    float* redc = (float*)su + 8448;      // [2048], in dead W region

    int tid = threadIdx.x;
    int lane = tid & 31, wid = tid >> 5;
    int g = lane >> 2, t4 = lane & 3;
    int wr = wid & 3, wc = wid >> 2;
    int b = blockIdx.y;
    int row0 = blockIdx.x * 64;
    int nrows = PP - row0; if (nrows > 64) nrows = 64;

    // ---- depot row copy (tile 0 only) ----
    if (blockIdx.x == 0 && tid < 32) {
        reinterpret_cast<float4*>(out + (size_t)b * 2001 * DD)[tid] =
            reinterpret_cast<const float4*>(emb + (size_t)b * 2001 * DD)[tid];
    }

    // ---- pack A tile (fp16) + load W1 + tour ids ----
    for (int i = tid; i < 64 * 32; i += 256) {
        int r = i >> 5, c4 = i & 31;
        float4 v = make_float4(0.f, 0.f, 0.f, 0.f);
        if (r < nrows)
            v = *reinterpret_cast<const float4*>(emb + (size_t)(b * 2001 + 1 + row0 + r) * DD + c4 * 4);
        Ah[r * 68 + 2 * c4]     = pack2(v.x, v.y);
        Ah[r * 68 + 2 * c4 + 1] = pack2(v.z, v.w);
    }
    for (int i = tid; i < 2048; i += 256) {
        int n = i >> 4, k4 = (i & 15) * 4;
        *reinterpret_cast<uint4*>(Ws + n * 68 + k4) =
            *reinterpret_cast<const uint4*>(g_W1p + n * 64 + k4);
    }
    if (tid < 64) {
        int t = 0;
        if (tid < nrows) t = tidx[b * PP + row0 + tid];
        ts[tid] = t;
    }
    __syncthreads();

    int r0 = wr * 16 + g, r1 = r0 + 8;

    float acc[8][4];
#pragma unroll
    for (int j = 0; j < 8; j++)
#pragma unroll
        for (int i = 0; i < 4; i++) acc[j][i] = 0.f;

    // ---- phase 1: acc = A @ W1a ----
#pragma unroll
    for (int s = 0; s < 8; s++) {
        unsigned a0 = Ah[r0 * 68 + s * 8 + t4];
        unsigned a1 = Ah[r1 * 68 + s * 8 + t4];
        unsigned a2 = Ah[r0 * 68 + s * 8 + t4 + 4];
        unsigned a3 = Ah[r1 * 68 + s * 8 + t4 + 4];
#pragma unroll
        for (int jt = 0; jt < 8; jt++) {
            int n = wc * 64 + jt * 8 + g;
            mma16816(acc[jt], a0, a1, a2, a3,
                     Ws[n * 68 + s * 8 + t4], Ws[n * 68 + s * 8 + t4 + 4]);
        }
    }
    __syncthreads();            // all phase-1 A and W1 reads complete

    // ---- overlap window: W2 copy + tb gather + H overlay write ----
    for (int i = tid; i < 2048; i += 256) {
        int n = i >> 4, k4 = (i & 15) * 4;
        *reinterpret_cast<uint4*>(Ws + n * 68 + k4) =
            *reinterpret_cast<const uint4*>(g_W2p + n * 64 + k4);
    }
    {
        const unsigned* base0 = g_tbh + (size_t)(b * TT + ts[r0]) * 64;
        const unsigned* base1 = g_tbh + (size_t)(b * TT + ts[r1]) * 64;
#pragma unroll
        for (int jt = 0; jt < 8; jt++) {
            int cp = wc * 32 + jt * 4 + t4;
            float2 tb0 = unpack2(base0[cp]);
            float2 tb1 = unpack2(base1[cp]);
            Ah[r0 * 68 + cp] = pack2(fmaxf(acc[jt][0] + tb0.x, 0.f),
                                     fmaxf(acc[jt][1] + tb0.y, 0.f));
            Ah[r1 * 68 + cp] = pack2(fmaxf(acc[jt][2] + tb1.x, 0.f),
                                     fmaxf(acc[jt][3] + tb1.y, 0.f));
#pragma unroll
            for (int i = 0; i < 4; i++) acc[jt][i] = 0.f;
        }
    }
    __syncthreads();            // H + W2 ready

    // ---- phase 2: acc = H @ W2 ----
#pragma unroll
    for (int s = 0; s < 8; s++) {
        unsigned a0 = Ah[r0 * 68 + s * 8 + t4];
        unsigned a1 = Ah[r1 * 68 + s * 8 + t4];
        unsigned a2 = Ah[r0 * 68 + s * 8 + t4 + 4];
        unsigned a3 = Ah[r1 * 68 + s * 8 + t4 + 4];
#pragma unroll
        for (int jt = 0; jt < 8; jt++) {
            int n = wc * 64 + jt * 8 + g;
            mma16816(acc[jt], a0, a1, a2, a3,
                     Ws[n * 68 + s * 8 + t4], Ws[n * 68 + s * 8 + t4 + 4]);
        }
    }
    __syncthreads();            // MMA smem reads done; whole smem reusable

    // ---- epilogue: added = acc + b2 + cust (exact f32 re-read) -> Ad ----
    {
        int rr0 = row0 + r0; if (rr0 > PP - 1) rr0 = PP - 1;
        int rr1 = row0 + r1; if (rr1 > PP - 1) rr1 = PP - 1;
        const float* e0 = emb + (size_t)(b * 2001 + 1 + rr0) * DD;
        const float* e1 = emb + (size_t)(b * 2001 + 1 + rr1) * DD;
#pragma unroll
        for (int jt = 0; jt < 8; jt++) {
            int colb = wc * 64 + jt * 8 + 2 * t4;
            float2 bb = *reinterpret_cast<const float2*>(b2 + colb);
            float2 c0 = *reinterpret_cast<const float2*>(e0 + colb);
            float2 c1 = *reinterpret_cast<const float2*>(e1 + colb);
            *reinterpret_cast<float2*>(Ad + r0 * 132 + colb) =
                make_float2(acc[jt][0] + bb.x + c0.x, acc[jt][1] + bb.y + c0.y);
            *reinterpret_cast<float2*>(Ad + r1 * 132 + colb) =
                make_float2(acc[jt][2] + bb.x + c1.x, acc[jt][3] + bb.y + c1.y);
        }
    }
    __syncthreads();

    // ---- column sum/sumsq over valid rows -> global atomics ----
    int c4 = tid & 31;        // 16B chunk within row
    int rg = tid >> 5;        // row group (8 rows each)
    {
        float s0 = 0.f, s1 = 0.f, s2 = 0.f, s3 = 0.f;
        float q0 = 0.f, q1 = 0.f, q2 = 0.f, q3 = 0.f;
#pragma unroll
        for (int m = 0; m < 8; m++) {
            int r = rg + m * 8;
            if (r < nrows) {
                float4 v = *reinterpret_cast<const float4*>(Ad + r * 132 + c4 * 4);
                s0 += v.x; s1 += v.y; s2 += v.z; s3 += v.w;
                q0 += v.x * v.x; q1 += v.y * v.y; q2 += v.z * v.z; q3 += v.w * v.w;
            }
        }
        float* rs = redc + rg * 128 + c4 * 4;
        rs[0] = s0; rs[1] = s1; rs[2] = s2; rs[3] = s3;
        float* rq = redc + 1024 + rg * 128 + c4 * 4;
        rq[0] = q0; rq[1] = q1; rq[2] = q2; rq[3] = q3;
        __syncthreads();
        if (tid < 128) {
            float s = 0.f;
#pragma unroll
            for (int m = 0; m < 8; m++) s += redc[m * 128 + tid];
            atomicAdd(&g_sum[b * DD + tid], s);
        } else {
            int col = tid - 128;
            float q = 0.f;
#pragma unroll
            for (int m = 0; m < 8; m++) q += redc[1024 + m * 128 + col];
            atomicAdd(&g_sumsq[b * DD + col], q);
        }
    }
    __syncthreads();

    // ---- publish arrival, spin until all tiles of batch b done ----
    if (tid == 0) {
        __threadfence();
        atomicAdd(&g_cnt[b], 1);
        volatile int* cp = g_cnt + b;
        while (*cp < TILES) __nanosleep(200);
    }
    __syncthreads();
    __threadfence();

    // ---- per-column scale/shift; normalize Ad -> out, coalesced ----
    {
        float4 S = __ldcg(reinterpret_cast<const float4*>(g_sum   + b * DD + c4 * 4));
        float4 Q = __ldcg(reinterpret_cast<const float4*>(g_sumsq + b * DD + c4 * 4));
        float4 G = *reinterpret_cast<const float4*>(gamma + c4 * 4);
        float4 Bt = *reinterpret_cast<const float4*>(beta + c4 * 4);
        const float inv = 1.f / PP;
        float m0 = S.x * inv, m1 = S.y * inv, m2 = S.z * inv, m3 = S.w * inv;
        float sc0 = G.x * rsqrtf(Q.x * inv - m0 * m0 + EPSL);
        float sc1 = G.y * rsqrtf(Q.y * inv - m1 * m1 + EPSL);
        float sc2 = G.z * rsqrtf(Q.z * inv - m2 * m2 + EPSL);
        float sc3 = G.w * rsqrtf(Q.w * inv - m3 * m3 + EPSL);
        float sh0 = Bt.x - m0 * sc0, sh1 = Bt.y - m1 * sc1;
        float sh2 = Bt.z - m2 * sc2, sh3 = Bt.w - m3 * sc3;
#pragma unroll
        for (int m = 0; m < 8; m++) {
            int r = rg + m * 8;
            if (r < nrows) {
                float4 v = *reinterpret_cast<const float4*>(Ad + r * 132 + c4 * 4);
                float4 o;
                o.x = v.x * sc0 + sh0;
                o.y = v.y * sc1 + sh1;
                o.z = v.z * sc2 + sh2;
                o.w = v.w * sc3 + sh3;
                *reinterpret_cast<float4*>(out + (size_t)(b * 2001 + 1 + row0 + r) * DD + c4 * 4) = o;
            }
        }
    }
}

// ---------------- launch ----------------
extern "C" void kernel_launch(void* const* d_in, const int* in_sizes, int n_in,
                              void* d_out, int out_size) {
    int ti = -1;
    for (int i = 0; i < n_in; i++)
        if (in_sizes[i] == BB * PP) { ti = i; break; }
    const int*   tidx  = (const int*)  d_in[ti];
    const float* emb   = (const float*)d_in[ti + 1];
    const float* W1    = (const float*)d_in[ti + 2];
    const float* b1    = (const float*)d_in[ti + 3];
    const float* W2    = (const float*)d_in[ti + 4];
    const float* b2    = (const float*)d_in[ti + 5];
    const float* gamma = (const float*)d_in[ti + 6];
    const float* beta  = (const float*)d_in[ti + 7];
    float* out = (float*)d_out;

    const int SMEM_TB   = TB_SMEM_U32 * 4;   // ~43.5 KB
    const int SMEM_MAIN = SMEM_U32 * 4;      // ~52.5 KB
    cudaFuncSetAttribute(k_tb,   cudaFuncAttributeMaxDynamicSharedMemorySize, SMEM_TB);
    cudaFuncSetAttribute(k_main, cudaFuncAttributeMaxDynamicSharedMemorySize, SMEM_MAIN);

    k_init<<<(BB * TT * DD + 255) / 256, 256>>>(W1, W2);
    k_seg<<<(BB * PP * 32 + 255) / 256, 256>>>(emb, tidx);
    k_tb<<<(BB * TT) / 32, 128, SMEM_TB>>>(b1);
    k_main<<<dim3(TILES, BB), 256, SMEM_MAIN>>>(emb, tidx, b2, gamma, beta, out);
}

// round 14
// speedup vs baseline: 1.2952x; 1.2952x over previous
#include <cuda_runtime.h>
#include <cuda_fp16.h>
#include <cstddef>
#include <cstdint>

#define BB 64
#define PP 2000
#define DD 128
#define TT 200
#define TILES 32
#define EPSL 1e-5f

// ---------------- scratch ----------------
__device__ float g_tour [BB * TT * DD];
__device__ unsigned g_tbh[BB * TT * 64];   // fp16x2 tb
__device__ float g_sum  [BB * DD];
__device__ float g_sumsq[BB * DD];
__device__ int   g_cnt  [BB];
// fp16x2 packed weights: [n][kp], kp in [0,64), pair = (W[2kp][n], W[2kp+1][n])
__device__ unsigned g_W1p[DD * 64];   // W1 rows [0,128)
__device__ unsigned g_Wbp[DD * 64];   // W1 rows [128,256)
__device__ unsigned g_W2p[DD * 64];

static __device__ __forceinline__ unsigned pack2(float v0, float v1) {
    __half2 h = __floats2half2_rn(v0, v1);
    return *reinterpret_cast<unsigned*>(&h);
}
static __device__ __forceinline__ float2 unpack2(unsigned u) {
    __half2 h = *reinterpret_cast<__half2*>(&u);
    return make_float2(__half2float(__low2half(h)), __half2float(__high2half(h)));
}

static __device__ __forceinline__ void mma16816(float* c, unsigned a0, unsigned a1,
                                                unsigned a2, unsigned a3,
                                                unsigned b0, unsigned b1) {
    asm volatile(
        "mma.sync.aligned.m16n8k16.row.col.f32.f16.f16.f32 "
        "{%0,%1,%2,%3}, {%4,%5,%6,%7}, {%8,%9}, {%0,%1,%2,%3};"
        : "+f"(c[0]), "+f"(c[1]), "+f"(c[2]), "+f"(c[3])
        : "r"(a0), "r"(a1), "r"(a2), "r"(a3), "r"(b0), "r"(b1));
}

// ---------------- K0: zero scratch (L2-warms g_tour for k_seg atomics) + pack ----------------
__global__ void k_init(const float* __restrict__ W1, const float* __restrict__ W2) {
    int i = blockIdx.x * blockDim.x + threadIdx.x;
    if (i < BB * TT * DD) g_tour[i] = 0.f;
    if (i < BB * DD) { g_sum[i] = 0.f; g_sumsq[i] = 0.f; }
    if (i < BB) g_cnt[i] = 0;
    if (i < 3 * DD * 64) {
        int m  = i >> 13;
        int n  = (i >> 6) & 127;
        int kp = i & 63;
        const float* W = (m == 0) ? W1 : (m == 1) ? (W1 + 128 * DD) : W2;
        unsigned p = pack2(W[(2 * kp) * DD + n], W[(2 * kp + 1) * DD + n]);
        if (m == 0)      g_W1p[n * 64 + kp] = p;
        else if (m == 1) g_Wbp[n * 64 + kp] = p;
        else             g_W2p[n * 64 + kp] = p;
    }
}

// ---------------- K1: segment sum ----------------
__global__ void k_seg(const float* __restrict__ emb, const int* __restrict__ tidx) {
    int i = blockIdx.x * blockDim.x + threadIdx.x;
    int d4 = i & 31;
    int r  = i >> 5;
    if (r >= BB * PP) return;
    int b = r / PP, p = r - b * PP;
    const float4 v = *reinterpret_cast<const float4*>(emb + (size_t)(b * 2001 + 1 + p) * DD + d4 * 4);
    int t = tidx[r];
    float4* dst = reinterpret_cast<float4*>(g_tour + (size_t)(b * TT + t) * DD + d4 * 4);
    atomicAdd(dst, v);
}

// ---------------- K2: tb = tour_emb @ W1b + b1 -> fp16 ----------------
#define TB_OFF_W (32 * 68)
#define TB_SMEM_U32 (TB_OFF_W + 128 * 68)
__global__ void __launch_bounds__(128, 5)
k_tb(const float* __restrict__ b1) {
    extern __shared__ unsigned su[];
    unsigned* As = su;
    unsigned* Ws = su + TB_OFF_W;
    int tid = threadIdx.x;
    int lane = tid & 31, wid = tid >> 5;
    int g = lane >> 2, t4 = lane & 3;
    int wr = wid & 1, wc = wid >> 1;
    int row0 = blockIdx.x * 32;

    for (int i = tid; i < 32 * 32; i += 128) {
        int r = i >> 5, c4 = i & 31;
        float4 v = *reinterpret_cast<const float4*>(g_tour + (size_t)(row0 + r) * DD + c4 * 4);
        As[r * 68 + 2 * c4]     = pack2(v.x, v.y);
        As[r * 68 + 2 * c4 + 1] = pack2(v.z, v.w);
    }
    for (int i = tid; i < 2048; i += 128) {
        int n = i >> 4, k4 = (i & 15) * 4;
        *reinterpret_cast<uint4*>(Ws + n * 68 + k4) =
            *reinterpret_cast<const uint4*>(g_Wbp + n * 64 + k4);
    }
    __syncthreads();

    float acc[8][4];
#pragma unroll
    for (int j = 0; j < 8; j++)
#pragma unroll
        for (int i = 0; i < 4; i++) acc[j][i] = 0.f;
    int r0 = wr * 16 + g, r1 = r0 + 8;

#pragma unroll
    for (int s = 0; s < 8; s++) {
        unsigned a0 = As[r0 * 68 + s * 8 + t4];
        unsigned a1 = As[r1 * 68 + s * 8 + t4];
        unsigned a2 = As[r0 * 68 + s * 8 + t4 + 4];
        unsigned a3 = As[r1 * 68 + s * 8 + t4 + 4];
#pragma unroll
        for (int jt = 0; jt < 8; jt++) {
            int n = wc * 64 + jt * 8 + g;
            mma16816(acc[jt], a0, a1, a2, a3,
                     Ws[n * 68 + s * 8 + t4], Ws[n * 68 + s * 8 + t4 + 4]);
        }
    }

#pragma unroll
    for (int jt = 0; jt < 8; jt++) {
        int colb = wc * 64 + jt * 8 + 2 * t4;
        int cp   = wc * 32 + jt * 4 + t4;
        float2 bb = *reinterpret_cast<const float2*>(b1 + colb);
        g_tbh[(size_t)(row0 + r0) * 64 + cp] = pack2(acc[jt][0] + bb.x, acc[jt][1] + bb.y);
        g_tbh[(size_t)(row0 + r1) * 64 + cp] = pack2(acc[jt][2] + bb.x, acc[jt][3] + bb.y);
    }
}

// ---------------- K3: fused MLP + residual + stats + spin + layernorm ----------------
// Warp tiling: 2 row-groups (wr: rows wr*32..wr*32+31, two m16 tiles) x
//              4 col-groups (wc: cols wc*32..wc*32+31, four n8 tiles).
// smem u32: A[64*68], H[64*68], W[128*68], ts[64]  (~70 KB -> 3 CTAs/SM)
// After phase2: Ad f32[64][132] aliases A+H; redc f32[2048] aliases W.
#define OFF_H  (64 * 68)
#define OFF_W  (2 * 64 * 68)
#define OFF_TS (2 * 64 * 68 + 128 * 68)
#define SMEM_U32 (OFF_TS + 64)

__global__ void __launch_bounds__(256, 3)
k_main(const float* __restrict__ emb, const int* __restrict__ tidx,
       const float* __restrict__ b2, const float* __restrict__ gamma,
       const float* __restrict__ beta, float* __restrict__ out) {
    extern __shared__ unsigned su[];
    unsigned* Ah = su;
    unsigned* Hs = su + OFF_H;
    unsigned* Ws = su + OFF_W;
    int* ts = (int*)(su + OFF_TS);
    float* Ad   = (float*)su;             // [64][132] after phase2
    float* redc = (float*)(su + OFF_W);   // [2048]

    int tid = threadIdx.x;
    int lane = tid & 31, wid = tid >> 5;
    int g = lane >> 2, t4 = lane & 3;
    int wr = wid & 1, wc = wid >> 1;      // 2 x 4 warp grid
    int b = blockIdx.y;
    int row0 = blockIdx.x * 64;
    int nrows = PP - row0; if (nrows > 64) nrows = 64;

    // this thread's 4 rows: q=0..3 -> wr*32 + q*8 + g  (q=2*mt+hi)
    int rq[4];
#pragma unroll
    for (int q = 0; q < 4; q++) rq[q] = wr * 32 + q * 8 + g;

    // ---- depot row copy (tile 0 only) ----
    if (blockIdx.x == 0 && tid < 32) {
        reinterpret_cast<float4*>(out + (size_t)b * 2001 * DD)[tid] =
            reinterpret_cast<const float4*>(emb + (size_t)b * 2001 * DD)[tid];
    }

    // ---- pack A tile (fp16) + load W1 + tour ids ----
    for (int i = tid; i < 64 * 32; i += 256) {
        int r = i >> 5, c4 = i & 31;
        float4 v = make_float4(0.f, 0.f, 0.f, 0.f);
        if (r < nrows)
            v = *reinterpret_cast<const float4*>(emb + (size_t)(b * 2001 + 1 + row0 + r) * DD + c4 * 4);
        Ah[r * 68 + 2 * c4]     = pack2(v.x, v.y);
        Ah[r * 68 + 2 * c4 + 1] = pack2(v.z, v.w);
    }
    for (int i = tid; i < 2048; i += 256) {
        int n = i >> 4, k4 = (i & 15) * 4;
        *reinterpret_cast<uint4*>(Ws + n * 68 + k4) =
            *reinterpret_cast<const uint4*>(g_W1p + n * 64 + k4);
    }
    if (tid < 64) {
        int t = 0;
        if (tid < nrows) t = tidx[b * PP + row0 + tid];
        ts[tid] = t;
    }
    __syncthreads();

    // ---- prefetch tb (fp16): 4 rows x 4 col-tiles ----
    unsigned tbv[4][4];
#pragma unroll
    for (int q = 0; q < 4; q++) {
        const unsigned* base = g_tbh + (size_t)(b * TT + ts[rq[q]]) * 64;
#pragma unroll
        for (int jt = 0; jt < 4; jt++)
            tbv[q][jt] = base[wc * 16 + jt * 4 + t4];
    }

    float acc[8][4];     // [mt*4 + jt][{rlo c0, rlo c1, rhi c0, rhi c1}]
#pragma unroll
    for (int j = 0; j < 8; j++)
#pragma unroll
        for (int i = 0; i < 4; i++) acc[j][i] = 0.f;

    // ---- phase 1: acc = A @ W1a ----
#pragma unroll
    for (int s = 0; s < 8; s++) {
        unsigned a[2][4];
#pragma unroll
        for (int mt = 0; mt < 2; mt++) {
            int rl = wr * 32 + mt * 16 + g;
            a[mt][0] = Ah[rl * 68 + s * 8 + t4];
            a[mt][1] = Ah[(rl + 8) * 68 + s * 8 + t4];
            a[mt][2] = Ah[rl * 68 + s * 8 + t4 + 4];
            a[mt][3] = Ah[(rl + 8) * 68 + s * 8 + t4 + 4];
        }
#pragma unroll
        for (int jt = 0; jt < 4; jt++) {
            int n = wc * 32 + jt * 8 + g;
            unsigned b0 = Ws[n * 68 + s * 8 + t4];
            unsigned b1 = Ws[n * 68 + s * 8 + t4 + 4];
            mma16816(acc[jt],     a[0][0], a[0][1], a[0][2], a[0][3], b0, b1);
            mma16816(acc[4 + jt], a[1][0], a[1][1], a[1][2], a[1][3], b0, b1);
        }
    }

    // ---- tb add + relu -> H (fp16) ----
#pragma unroll
    for (int mt = 0; mt < 2; mt++) {
        int rl = wr * 32 + mt * 16 + g, rh = rl + 8;
#pragma unroll
        for (int jt = 0; jt < 4; jt++) {
            int cp = wc * 16 + jt * 4 + t4;
            float2 tl = unpack2(tbv[mt * 2][jt]);
            float2 th = unpack2(tbv[mt * 2 + 1][jt]);
            float* A4 = acc[mt * 4 + jt];
            Hs[rl * 68 + cp] = pack2(fmaxf(A4[0] + tl.x, 0.f), fmaxf(A4[1] + tl.y, 0.f));
            Hs[rh * 68 + cp] = pack2(fmaxf(A4[2] + th.x, 0.f), fmaxf(A4[3] + th.y, 0.f));
            A4[0] = A4[1] = A4[2] = A4[3] = 0.f;
        }
    }
    __syncthreads();            // H complete; W1 reads done

    // ---- load W2 ----
    for (int i = tid; i < 2048; i += 256) {
        int n = i >> 4, k4 = (i & 15) * 4;
        *reinterpret_cast<uint4*>(Ws + n * 68 + k4) =
            *reinterpret_cast<const uint4*>(g_W2p + n * 64 + k4);
    }
    __syncthreads();

    // ---- prefetch residual cust (exact f32): 4 rows x 4 col-pairs ----
    float2 cv[4][4];
#pragma unroll
    for (int q = 0; q < 4; q++) {
        int rr = row0 + rq[q]; if (rr > PP - 1) rr = PP - 1;
        const float* e = emb + (size_t)(b * 2001 + 1 + rr) * DD;
#pragma unroll
        for (int jt = 0; jt < 4; jt++)
            cv[q][jt] = *reinterpret_cast<const float2*>(e + wc * 32 + jt * 8 + 2 * t4);
    }

    // ---- phase 2: acc = H @ W2 ----
#pragma unroll
    for (int s = 0; s < 8; s++) {
        unsigned a[2][4];
#pragma unroll
        for (int mt = 0; mt < 2; mt++) {
            int rl = wr * 32 + mt * 16 + g;
            a[mt][0] = Hs[rl * 68 + s * 8 + t4];
            a[mt][1] = Hs[(rl + 8) * 68 + s * 8 + t4];
            a[mt][2] = Hs[rl * 68 + s * 8 + t4 + 4];
            a[mt][3] = Hs[(rl + 8) * 68 + s * 8 + t4 + 4];
        }
#pragma unroll
        for (int jt = 0; jt < 4; jt++) {
            int n = wc * 32 + jt * 8 + g;
            unsigned b0 = Ws[n * 68 + s * 8 + t4];
            unsigned b1 = Ws[n * 68 + s * 8 + t4 + 4];
            mma16816(acc[jt],     a[0][0], a[0][1], a[0][2], a[0][3], b0, b1);
            mma16816(acc[4 + jt], a[1][0], a[1][1], a[1][2], a[1][3], b0, b1);
        }
    }
    __syncthreads();            // MMA smem reads done; Ah/Hs/Ws reusable

    // ---- epilogue: added = acc + b2 + cust -> Ad (coalesced layout source) ----
#pragma unroll
    for (int mt = 0; mt < 2; mt++) {
        int rl = wr * 32 + mt * 16 + g, rh = rl + 8;
#pragma unroll
        for (int jt = 0; jt < 4; jt++) {
            int colb = wc * 32 + jt * 8 + 2 * t4;
            float2 bb = *reinterpret_cast<const float2*>(b2 + colb);
            float* A4 = acc[mt * 4 + jt];
            *reinterpret_cast<float2*>(Ad + rl * 132 + colb) =
                make_float2(A4[0] + bb.x + cv[mt * 2][jt].x, A4[1] + bb.y + cv[mt * 2][jt].y);
            *reinterpret_cast<float2*>(Ad + rh * 132 + colb) =
                make_float2(A4[2] + bb.x + cv[mt * 2 + 1][jt].x, A4[3] + bb.y + cv[mt * 2 + 1][jt].y);
        }
    }
    __syncthreads();

    // ---- column sum/sumsq over valid rows -> global atomics ----
    int c4 = tid & 31;        // 16B chunk within row
    int rg = tid >> 5;        // row group (8 rows each)
    {
        float s0 = 0.f, s1 = 0.f, s2 = 0.f, s3 = 0.f;
        float q0 = 0.f, q1 = 0.f, q2 = 0.f, q3 = 0.f;
#pragma unroll
        for (int m = 0; m < 8; m++) {
            int r = rg + m * 8;
            if (r < nrows) {
                float4 v = *reinterpret_cast<const float4*>(Ad + r * 132 + c4 * 4);
                s0 += v.x; s1 += v.y; s2 += v.z; s3 += v.w;
                q0 += v.x * v.x; q1 += v.y * v.y; q2 += v.z * v.z; q3 += v.w * v.w;
            }
        }
        float* rs = redc + rg * 128 + c4 * 4;
        rs[0] = s0; rs[1] = s1; rs[2] = s2; rs[3] = s3;
        float* rqp = redc + 1024 + rg * 128 + c4 * 4;
        rqp[0] = q0; rqp[1] = q1; rqp[2] = q2; rqp[3] = q3;
        __syncthreads();
        if (tid < 128) {
            float s = 0.f;
#pragma unroll
            for (int m = 0; m < 8; m++) s += redc[m * 128 + tid];
            atomicAdd(&g_sum[b * DD + tid], s);
        } else {
            int col = tid - 128;
            float q = 0.f;
#pragma unroll
            for (int m = 0; m < 8; m++) q += redc[1024 + m * 128 + col];
            atomicAdd(&g_sumsq[b * DD + col], q);
        }
    }
    __syncthreads();

    // ---- publish arrival, spin until all tiles of batch b done ----
    if (tid == 0) {
        __threadfence();
        atomicAdd(&g_cnt[b], 1);
        volatile int* cp = g_cnt + b;
        while (*cp < TILES) __nanosleep(200);
    }
    __syncthreads();
    __threadfence();

    // ---- per-column scale/shift; normalize Ad -> out, coalesced ----
    {
        float4 S = __ldcg(reinterpret_cast<const float4*>(g_sum   + b * DD + c4 * 4));
        float4 Q = __ldcg(reinterpret_cast<const float4*>(g_sumsq + b * DD + c4 * 4));
        float4 G = *reinterpret_cast<const float4*>(gamma + c4 * 4);
        float4 Bt = *reinterpret_cast<const float4*>(beta + c4 * 4);
        const float inv = 1.f / PP;
        float m0 = S.x * inv, m1 = S.y * inv, m2 = S.z * inv, m3 = S.w * inv;
        float sc0 = G.x * rsqrtf(Q.x * inv - m0 * m0 + EPSL);
        float sc1 = G.y * rsqrtf(Q.y * inv - m1 * m1 + EPSL);
        float sc2 = G.z * rsqrtf(Q.z * inv - m2 * m2 + EPSL);
        float sc3 = G.w * rsqrtf(Q.w * inv - m3 * m3 + EPSL);
        float sh0 = Bt.x - m0 * sc0, sh1 = Bt.y - m1 * sc1;
        float sh2 = Bt.z - m2 * sc2, sh3 = Bt.w - m3 * sc3;
#pragma unroll
        for (int m = 0; m < 8; m++) {
            int r = rg + m * 8;
            if (r < nrows) {
                float4 v = *reinterpret_cast<const float4*>(Ad + r * 132 + c4 * 4);
                float4 o;
                o.x = v.x * sc0 + sh0;
                o.y = v.y * sc1 + sh1;
                o.z = v.z * sc2 + sh2;
                o.w = v.w * sc3 + sh3;
                *reinterpret_cast<float4*>(out + (size_t)(b * 2001 + 1 + row0 + r) * DD + c4 * 4) = o;
            }
        }
    }
}

// ---------------- launch ----------------
extern "C" void kernel_launch(void* const* d_in, const int* in_sizes, int n_in,
                              void* d_out, int out_size) {
    int ti = -1;
    for (int i = 0; i < n_in; i++)
        if (in_sizes[i] == BB * PP) { ti = i; break; }
    const int*   tidx  = (const int*)  d_in[ti];
    const float* emb   = (const float*)d_in[ti + 1];
    const float* W1    = (const float*)d_in[ti + 2];
    const float* b1    = (const float*)d_in[ti + 3];
    const float* W2    = (const float*)d_in[ti + 4];
    const float* b2    = (const float*)d_in[ti + 5];
    const float* gamma = (const float*)d_in[ti + 6];
    const float* beta  = (const float*)d_in[ti + 7];
    float* out = (float*)d_out;

    const int SMEM_TB   = TB_SMEM_U32 * 4;   // ~43.5 KB
    const int SMEM_MAIN = SMEM_U32 * 4;      // ~70 KB
    cudaFuncSetAttribute(k_tb,   cudaFuncAttributeMaxDynamicSharedMemorySize, SMEM_TB);
    cudaFuncSetAttribute(k_main, cudaFuncAttributeMaxDynamicSharedMemorySize, SMEM_MAIN);

    k_init<<<(BB * TT * DD + 255) / 256, 256>>>(W1, W2);
    k_seg<<<(BB * PP * 32 + 255) / 256, 256>>>(emb, tidx);
    k_tb<<<(BB * TT) / 32, 128, SMEM_TB>>>(b1);
    k_main<<<dim3(TILES, BB), 256, SMEM_MAIN>>>(emb, tidx, b2, gamma, beta, out);
}

// round 15
// speedup vs baseline: 1.4892x; 1.1498x over previous
#include <cuda_runtime.h>
#include <cuda_fp16.h>
#include <cstddef>
#include <cstdint>

#define BB 64
#define PP 2000
#define DD 128
#define TT 200
#define TILES 32
#define EPSL 1e-5f

// ---------------- scratch ----------------
__device__ float g_tour [BB * TT * DD];
__device__ unsigned g_tbh[BB * TT * 64];   // fp16x2 tb
__device__ float g_sum  [BB * DD];
__device__ float g_sumsq[BB * DD];
__device__ int   g_cnt  [BB];
// fp16x2 packed weights: [n][kp], kp in [0,64), pair = (W[2kp][n], W[2kp+1][n])
__device__ unsigned g_W1p[DD * 64];   // W1 rows [0,128)
__device__ unsigned g_Wbp[DD * 64];   // W1 rows [128,256)
__device__ unsigned g_W2p[DD * 64];

static __device__ __forceinline__ unsigned pack2(float v0, float v1) {
    __half2 h = __floats2half2_rn(v0, v1);
    return *reinterpret_cast<unsigned*>(&h);
}
static __device__ __forceinline__ float2 unpack2(unsigned u) {
    __half2 h = *reinterpret_cast<__half2*>(&u);
    return make_float2(__half2float(__low2half(h)), __half2float(__high2half(h)));
}

static __device__ __forceinline__ void mma16816(float* c, unsigned a0, unsigned a1,
                                                unsigned a2, unsigned a3,
                                                unsigned b0, unsigned b1) {
    asm volatile(
        "mma.sync.aligned.m16n8k16.row.col.f32.f16.f16.f32 "
        "{%0,%1,%2,%3}, {%4,%5,%6,%7}, {%8,%9}, {%0,%1,%2,%3};"
        : "+f"(c[0]), "+f"(c[1]), "+f"(c[2]), "+f"(c[3])
        : "r"(a0), "r"(a1), "r"(a2), "r"(a3), "r"(b0), "r"(b1));
}

// ---------------- K0: zero scratch (L2-warms g_tour for k_seg atomics) + pack ----------------
__global__ void k_init(const float* __restrict__ W1, const float* __restrict__ W2) {
    int i = blockIdx.x * blockDim.x + threadIdx.x;
    if (i < BB * TT * DD) g_tour[i] = 0.f;
    if (i < BB * DD) { g_sum[i] = 0.f; g_sumsq[i] = 0.f; }
    if (i < BB) g_cnt[i] = 0;
    if (i < 3 * DD * 64) {
        int m  = i >> 13;
        int n  = (i >> 6) & 127;
        int kp = i & 63;
        const float* W = (m == 0) ? W1 : (m == 1) ? (W1 + 128 * DD) : W2;
        unsigned p = pack2(W[(2 * kp) * DD + n], W[(2 * kp + 1) * DD + n]);
        if (m == 0)      g_W1p[n * 64 + kp] = p;
        else if (m == 1) g_Wbp[n * 64 + kp] = p;
        else             g_W2p[n * 64 + kp] = p;
    }
}

// ---------------- K1: segment sum ----------------
__global__ void k_seg(const float* __restrict__ emb, const int* __restrict__ tidx) {
    int i = blockIdx.x * blockDim.x + threadIdx.x;
    int d4 = i & 31;
    int r  = i >> 5;
    if (r >= BB * PP) return;
    int b = r / PP, p = r - b * PP;
    const float4 v = *reinterpret_cast<const float4*>(emb + (size_t)(b * 2001 + 1 + p) * DD + d4 * 4);
    int t = tidx[r];
    float4* dst = reinterpret_cast<float4*>(g_tour + (size_t)(b * TT + t) * DD + d4 * 4);
    atomicAdd(dst, v);
}

// ---------------- K2: tb = tour_emb @ W1b + b1 -> fp16 ----------------
#define TB_OFF_W (32 * 68)
#define TB_SMEM_U32 (TB_OFF_W + 128 * 68)
__global__ void __launch_bounds__(128, 5)
k_tb(const float* __restrict__ b1) {
    extern __shared__ unsigned su[];
    unsigned* As = su;
    unsigned* Ws = su + TB_OFF_W;
    int tid = threadIdx.x;
    int lane = tid & 31, wid = tid >> 5;
    int g = lane >> 2, t4 = lane & 3;
    int wr = wid & 1, wc = wid >> 1;
    int row0 = blockIdx.x * 32;

    for (int i = tid; i < 32 * 32; i += 128) {
        int r = i >> 5, c4 = i & 31;
        float4 v = *reinterpret_cast<const float4*>(g_tour + (size_t)(row0 + r) * DD + c4 * 4);
        As[r * 68 + 2 * c4]     = pack2(v.x, v.y);
        As[r * 68 + 2 * c4 + 1] = pack2(v.z, v.w);
    }
    for (int i = tid; i < 2048; i += 128) {
        int n = i >> 4, k4 = (i & 15) * 4;
        *reinterpret_cast<uint4*>(Ws + n * 68 + k4) =
            *reinterpret_cast<const uint4*>(g_Wbp + n * 64 + k4);
    }
    __syncthreads();

    float acc[8][4];
#pragma unroll
    for (int j = 0; j < 8; j++)
#pragma unroll
        for (int i = 0; i < 4; i++) acc[j][i] = 0.f;
    int r0 = wr * 16 + g, r1 = r0 + 8;

#pragma unroll
    for (int s = 0; s < 8; s++) {
        unsigned a0 = As[r0 * 68 + s * 8 + t4];
        unsigned a1 = As[r1 * 68 + s * 8 + t4];
        unsigned a2 = As[r0 * 68 + s * 8 + t4 + 4];
        unsigned a3 = As[r1 * 68 + s * 8 + t4 + 4];
#pragma unroll
        for (int jt = 0; jt < 8; jt++) {
            int n = wc * 64 + jt * 8 + g;
            mma16816(acc[jt], a0, a1, a2, a3,
                     Ws[n * 68 + s * 8 + t4], Ws[n * 68 + s * 8 + t4 + 4]);
        }
    }

#pragma unroll
    for (int jt = 0; jt < 8; jt++) {
        int colb = wc * 64 + jt * 8 + 2 * t4;
        int cp   = wc * 32 + jt * 4 + t4;
        float2 bb = *reinterpret_cast<const float2*>(b1 + colb);
        g_tbh[(size_t)(row0 + r0) * 64 + cp] = pack2(acc[jt][0] + bb.x, acc[jt][1] + bb.y);
        g_tbh[(size_t)(row0 + r1) * 64 + cp] = pack2(acc[jt][2] + bb.x, acc[jt][3] + bb.y);
    }
}

// ---------------- K3: fused MLP + residual + stats + spin + layernorm ----------------
// Warp tiling 2x4 (wr rows, wc cols). H overlays A. 52.5 KB smem -> 4 CTAs/SM.
// After phase2: Ad f32[64][132] = su[0..8448); redc f32[512] = su[8448..8960).
#define OFF_W  (64 * 68)
#define OFF_TS (OFF_W + 128 * 68)
#define SMEM_U32 (OFF_TS + 64)

__global__ void __launch_bounds__(256, 4)
k_main(const float* __restrict__ emb, const int* __restrict__ tidx,
       const float* __restrict__ b2, const float* __restrict__ gamma,
       const float* __restrict__ beta, float* __restrict__ out) {
    extern __shared__ unsigned su[];
    unsigned* Ah = su;                    // A fp16, overlaid by H fp16
    unsigned* Ws = su + OFF_W;
    int* ts = (int*)(su + OFF_TS);
    float* Ad   = (float*)su;             // [64][132] after phase2
    float* redc = (float*)(su + 8448);    // [512] in dead W tail

    int tid = threadIdx.x;
    int lane = tid & 31, wid = tid >> 5;
    int g = lane >> 2, t4 = lane & 3;
    int wr = wid & 1, wc = wid >> 1;      // 2 x 4 warp grid
    int b = blockIdx.y;
    int row0 = blockIdx.x * 64;
    int nrows = PP - row0; if (nrows > 64) nrows = 64;

    // ---- depot row copy (tile 0 only) ----
    if (blockIdx.x == 0 && tid < 32) {
        reinterpret_cast<float4*>(out + (size_t)b * 2001 * DD)[tid] =
            reinterpret_cast<const float4*>(emb + (size_t)b * 2001 * DD)[tid];
    }

    // ---- pack A tile (fp16) + load W1 + tour ids ----
    for (int i = tid; i < 64 * 32; i += 256) {
        int r = i >> 5, c4 = i & 31;
        float4 v = make_float4(0.f, 0.f, 0.f, 0.f);
        if (r < nrows)
            v = *reinterpret_cast<const float4*>(emb + (size_t)(b * 2001 + 1 + row0 + r) * DD + c4 * 4);
        Ah[r * 68 + 2 * c4]     = pack2(v.x, v.y);
        Ah[r * 68 + 2 * c4 + 1] = pack2(v.z, v.w);
    }
    for (int i = tid; i < 2048; i += 256) {
        int n = i >> 4, k4 = (i & 15) * 4;
        *reinterpret_cast<uint4*>(Ws + n * 68 + k4) =
            *reinterpret_cast<const uint4*>(g_W1p + n * 64 + k4);
    }
    if (tid < 64) {
        int t = 0;
        if (tid < nrows) t = tidx[b * PP + row0 + tid];
        ts[tid] = t;
    }
    __syncthreads();

    float acc[8][4];     // [mt*4 + jt][{rlo c0, rlo c1, rhi c0, rhi c1}]
#pragma unroll
    for (int j = 0; j < 8; j++)
#pragma unroll
        for (int i = 0; i < 4; i++) acc[j][i] = 0.f;

    // ---- phase 1: acc = A @ W1a ----
#pragma unroll
    for (int s = 0; s < 8; s++) {
        unsigned a[2][4];
#pragma unroll
        for (int mt = 0; mt < 2; mt++) {
            int rl = wr * 32 + mt * 16 + g;
            a[mt][0] = Ah[rl * 68 + s * 8 + t4];
            a[mt][1] = Ah[(rl + 8) * 68 + s * 8 + t4];
            a[mt][2] = Ah[rl * 68 + s * 8 + t4 + 4];
            a[mt][3] = Ah[(rl + 8) * 68 + s * 8 + t4 + 4];
        }
#pragma unroll
        for (int jt = 0; jt < 4; jt++) {
            int n = wc * 32 + jt * 8 + g;
            unsigned b0 = Ws[n * 68 + s * 8 + t4];
            unsigned b1 = Ws[n * 68 + s * 8 + t4 + 4];
            mma16816(acc[jt],     a[0][0], a[0][1], a[0][2], a[0][3], b0, b1);
            mma16816(acc[4 + jt], a[1][0], a[1][1], a[1][2], a[1][3], b0, b1);
        }
    }
    __syncthreads();            // all phase-1 A and W1 reads complete

    // ---- overlap window: W2 copy + tb gather (inline) + H overlay write ----
    for (int i = tid; i < 2048; i += 256) {
        int n = i >> 4, k4 = (i & 15) * 4;
        *reinterpret_cast<uint4*>(Ws + n * 68 + k4) =
            *reinterpret_cast<const uint4*>(g_W2p + n * 64 + k4);
    }
#pragma unroll
    for (int mt = 0; mt < 2; mt++) {
        int rl = wr * 32 + mt * 16 + g, rh = rl + 8;
        const unsigned* bl = g_tbh + (size_t)(b * TT + ts[rl]) * 64;
        const unsigned* bh = g_tbh + (size_t)(b * TT + ts[rh]) * 64;
#pragma unroll
        for (int jt = 0; jt < 4; jt++) {
            int cp = wc * 16 + jt * 4 + t4;
            float2 tl = unpack2(bl[cp]);
            float2 th = unpack2(bh[cp]);
            float* A4 = acc[mt * 4 + jt];
            Ah[rl * 68 + cp] = pack2(fmaxf(A4[0] + tl.x, 0.f), fmaxf(A4[1] + tl.y, 0.f));
            Ah[rh * 68 + cp] = pack2(fmaxf(A4[2] + th.x, 0.f), fmaxf(A4[3] + th.y, 0.f));
            A4[0] = A4[1] = A4[2] = A4[3] = 0.f;
        }
    }
    __syncthreads();            // H + W2 ready

    // ---- phase 2: acc = H @ W2 ----
#pragma unroll
    for (int s = 0; s < 8; s++) {
        unsigned a[2][4];
#pragma unroll
        for (int mt = 0; mt < 2; mt++) {
            int rl = wr * 32 + mt * 16 + g;
            a[mt][0] = Ah[rl * 68 + s * 8 + t4];
            a[mt][1] = Ah[(rl + 8) * 68 + s * 8 + t4];
            a[mt][2] = Ah[rl * 68 + s * 8 + t4 + 4];
            a[mt][3] = Ah[(rl + 8) * 68 + s * 8 + t4 + 4];
        }
#pragma unroll
        for (int jt = 0; jt < 4; jt++) {
            int n = wc * 32 + jt * 8 + g;
            unsigned b0 = Ws[n * 68 + s * 8 + t4];
            unsigned b1 = Ws[n * 68 + s * 8 + t4 + 4];
            mma16816(acc[jt],     a[0][0], a[0][1], a[0][2], a[0][3], b0, b1);
            mma16816(acc[4 + jt], a[1][0], a[1][1], a[1][2], a[1][3], b0, b1);
        }
    }
    __syncthreads();            // MMA smem reads done; whole smem reusable

    // ---- epilogue: acc += b2 + cust (inline f32 re-read); write Ad; local col sums ----
    float sl[4][2], ql[4][2];
#pragma unroll
    for (int jt = 0; jt < 4; jt++)
#pragma unroll
        for (int par = 0; par < 2; par++) { sl[jt][par] = 0.f; ql[jt][par] = 0.f; }

#pragma unroll
    for (int mt = 0; mt < 2; mt++) {
        int rl = wr * 32 + mt * 16 + g, rh = rl + 8;
        int rrl = row0 + rl; if (rrl > PP - 1) rrl = PP - 1;
        int rrh = row0 + rh; if (rrh > PP - 1) rrh = PP - 1;
        bool vl = rl < nrows, vh = rh < nrows;
        const float* el = emb + (size_t)(b * 2001 + 1 + rrl) * DD;
        const float* eh = emb + (size_t)(b * 2001 + 1 + rrh) * DD;
#pragma unroll
        for (int jt = 0; jt < 4; jt++) {
            int colb = wc * 32 + jt * 8 + 2 * t4;
            float2 bb = *reinterpret_cast<const float2*>(b2 + colb);
            float2 cl = *reinterpret_cast<const float2*>(el + colb);
            float2 ch = *reinterpret_cast<const float2*>(eh + colb);
            float* A4 = acc[mt * 4 + jt];
            A4[0] += bb.x + cl.x;  A4[1] += bb.y + cl.y;
            A4[2] += bb.x + ch.x;  A4[3] += bb.y + ch.y;
            *reinterpret_cast<float2*>(Ad + rl * 132 + colb) = make_float2(A4[0], A4[1]);
            *reinterpret_cast<float2*>(Ad + rh * 132 + colb) = make_float2(A4[2], A4[3]);
            if (vl) {
                sl[jt][0] += A4[0];          sl[jt][1] += A4[1];
                ql[jt][0] += A4[0] * A4[0];  ql[jt][1] += A4[1] * A4[1];
            }
            if (vh) {
                sl[jt][0] += A4[2];          sl[jt][1] += A4[3];
                ql[jt][0] += A4[2] * A4[2];  ql[jt][1] += A4[3] * A4[3];
            }
        }
    }

    // ---- shuffle-reduce over g (lanes 4g+t4), then redc + global atomics ----
#pragma unroll
    for (int jt = 0; jt < 4; jt++)
#pragma unroll
        for (int par = 0; par < 2; par++) {
#pragma unroll
            for (int mask = 4; mask < 32; mask <<= 1) {
                sl[jt][par] += __shfl_xor_sync(0xffffffffu, sl[jt][par], mask);
                ql[jt][par] += __shfl_xor_sync(0xffffffffu, ql[jt][par], mask);
            }
        }
    if (g == 0) {
#pragma unroll
        for (int jt = 0; jt < 4; jt++)
#pragma unroll
            for (int par = 0; par < 2; par++) {
                int col = wc * 32 + jt * 8 + 2 * t4 + par;
                redc[wr * 128 + col]       = sl[jt][par];
                redc[256 + wr * 128 + col] = ql[jt][par];
            }
    }
    __syncthreads();
    if (tid < 128) {
        atomicAdd(&g_sum[b * DD + tid], redc[tid] + redc[128 + tid]);
    } else {
        int col = tid - 128;
        atomicAdd(&g_sumsq[b * DD + col], redc[256 + col] + redc[384 + col]);
    }
    __syncthreads();

    // ---- publish arrival, spin until all tiles of batch b done ----
    if (tid == 0) {
        __threadfence();
        atomicAdd(&g_cnt[b], 1);
        volatile int* cp = g_cnt + b;
        while (*cp < TILES) __nanosleep(200);
    }
    __syncthreads();
    __threadfence();

    // ---- per-column scale/shift; normalize Ad -> out, coalesced ----
    {
        int c4 = tid & 31, rg = tid >> 5;
        float4 S = __ldcg(reinterpret_cast<const float4*>(g_sum   + b * DD + c4 * 4));
        float4 Q = __ldcg(reinterpret_cast<const float4*>(g_sumsq + b * DD + c4 * 4));
        float4 G = *reinterpret_cast<const float4*>(gamma + c4 * 4);
        float4 Bt = *reinterpret_cast<const float4*>(beta + c4 * 4);
        const float inv = 1.f / PP;
        float m0 = S.x * inv, m1 = S.y * inv, m2 = S.z * inv, m3 = S.w * inv;
        float sc0 = G.x * rsqrtf(Q.x * inv - m0 * m0 + EPSL);
        float sc1 = G.y * rsqrtf(Q.y * inv - m1 * m1 + EPSL);
        float sc2 = G.z * rsqrtf(Q.z * inv - m2 * m2 + EPSL);
        float sc3 = G.w * rsqrtf(Q.w * inv - m3 * m3 + EPSL);
        float sh0 = Bt.x - m0 * sc0, sh1 = Bt.y - m1 * sc1;
        float sh2 = Bt.z - m2 * sc2, sh3 = Bt.w - m3 * sc3;
#pragma unroll
        for (int m = 0; m < 8; m++) {
            int r = rg + m * 8;
            if (r < nrows) {
                float4 v = *reinterpret_cast<const float4*>(Ad + r * 132 + c4 * 4);
                float4 o;
                o.x = v.x * sc0 + sh0;
                o.y = v.y * sc1 + sh1;
                o.z = v.z * sc2 + sh2;
                o.w = v.w * sc3 + sh3;
                *reinterpret_cast<float4*>(out + (size_t)(b * 2001 + 1 + row0 + r) * DD + c4 * 4) = o;
            }
        }
    }
}

// ---------------- launch ----------------
extern "C" void kernel_launch(void* const* d_in, const int* in_sizes, int n_in,
                              void* d_out, int out_size) {
    int ti = -1;
    for (int i = 0; i < n_in; i++)
        if (in_sizes[i] == BB * PP) { ti = i; break; }
    const int*   tidx  = (const int*)  d_in[ti];
    const float* emb   = (const float*)d_in[ti + 1];
    const float* W1    = (const float*)d_in[ti + 2];
    const float* b1    = (const float*)d_in[ti + 3];
    const float* W2    = (const float*)d_in[ti + 4];
    const float* b2    = (const float*)d_in[ti + 5];
    const float* gamma = (const float*)d_in[ti + 6];
    const float* beta  = (const float*)d_in[ti + 7];
    float* out = (float*)d_out;

    const int SMEM_TB   = TB_SMEM_U32 * 4;   // ~43.5 KB
    const int SMEM_MAIN = SMEM_U32 * 4;      // ~52.5 KB
    cudaFuncSetAttribute(k_tb,   cudaFuncAttributeMaxDynamicSharedMemorySize, SMEM_TB);
    cudaFuncSetAttribute(k_main, cudaFuncAttributeMaxDynamicSharedMemorySize, SMEM_MAIN);

    k_init<<<(BB * TT * DD + 255) / 256, 256>>>(W1, W2);
    k_seg<<<(BB * PP * 32 + 255) / 256, 256>>>(emb, tidx);
    k_tb<<<(BB * TT) / 32, 128, SMEM_TB>>>(b1);
    k_main<<<dim3(TILES, BB), 256, SMEM_MAIN>>>(emb, tidx, b2, gamma, beta, out);
}